// round 14
// baseline (speedup 1.0000x reference)
#include <cuda_runtime.h>
#include <cuda_bf16.h>
#include <math.h>
#include <stdint.h>

// Problem constants
#define Dm     256
#define D2     512
#define Sn     128
#define Lh     256
#define NROWS  1024
#define HROWS  512
#define LN2F   0.69314718055994531f
#define SROW   20                 // smem row stride in uint32 words
#define A32W   (32 * SROW)
#define B64W   (64 * SROW)
#define GSTAGE (A32W + B64W)      // gemm32 per-stage words
#define SSTAGE (A32W + 4 * B64W)  // ssm per-stage words
#define NCTA   296                // 2 CTAs/SM on 148 SMs

// ---------------- scratch ----------------
__device__ __nv_bfloat16 g_XNbf[NROWS * Dm];
__device__ __nv_bfloat16 g_Wibf[D2 * Dm];
__device__ __nv_bfloat16 g_Wdbf[D2 * Dm];
__device__ __nv_bfloat16 g_W1bf[D2 * D2];
__device__ __nv_bfloat16 g_W2bf[Sn * D2];
__device__ __nv_bfloat16 g_Pbf[NROWS * D2];
__device__ __nv_bfloat16 g_XCbf[NROWS * D2];
__device__ float         g_DELTA[NROWS * D2];
__device__ __nv_bfloat16 g_BMbf[NROWS * Sn];
__device__ __nv_bfloat16 g_Ebf[4 * D2 * Sn];
__device__ float         g_XS[NROWS * D2];
__device__ float         g_RES[HROWS * D2];
__device__ unsigned      g_barctr[8];   // monotonic grid barriers
__device__ unsigned      g_wctr[8];     // monotonic work-steal counters

__device__ __forceinline__ float silu_f(float v) { return v / (1.f + expf(-v)); }
__device__ __forceinline__ float softplus_f(float v) {
    return fmaxf(v, 0.f) + log1pf(expf(-fabsf(v)));
}
__device__ __forceinline__ uint32_t pk(float a, float b) {
    __nv_bfloat162 h = __floats2bfloat162_rn(a, b);
    return *reinterpret_cast<uint32_t*>(&h);
}
__device__ __forceinline__ uint4 pack8(float4 u, float4 v) {
    return make_uint4(pk(u.x, u.y), pk(u.z, u.w), pk(v.x, v.y), pk(v.z, v.w));
}
__device__ __forceinline__ void mma_bf16(float c[4],
    uint32_t a0, uint32_t a1, uint32_t a2, uint32_t a3,
    uint32_t b0, uint32_t b1)
{
    asm("mma.sync.aligned.m16n8k16.row.col.f32.bf16.bf16.f32 "
        "{%0,%1,%2,%3}, {%4,%5,%6,%7}, {%8,%9}, {%0,%1,%2,%3};"
        : "+f"(c[0]), "+f"(c[1]), "+f"(c[2]), "+f"(c[3])
        : "r"(a0), "r"(a1), "r"(a2), "r"(a3), "r"(b0), "r"(b1));
}
__device__ __forceinline__ void cpa16(uint32_t saddr, const void* g) {
    asm volatile("cp.async.ca.shared.global [%0], [%1], 16;"
                 :: "r"(saddr), "l"(g) : "memory");
}
#define CP_COMMIT() asm volatile("cp.async.commit_group;" ::: "memory")
#define CP_WAIT1()  asm volatile("cp.async.wait_group 1;" ::: "memory")

// ---------------- grid barrier (monotonic, no reset needed) ------------------
__device__ __forceinline__ void grid_barrier(int s) {
    __syncthreads();
    __threadfence();
    if (threadIdx.x == 0) {
        unsigned a = atomicAdd(&g_barctr[s], 1u);
        unsigned target = (a / (unsigned)NCTA + 1u) * (unsigned)NCTA;
        volatile unsigned* p = &g_barctr[s];
        while (*p < target) __nanosleep(64);
        __threadfence();
    }
    __syncthreads();
}

// ---------------- work stealing: tile idx or -1 (monotonic counters) ---------
__device__ __forceinline__ int grab_tile(int s, int n) {
    __shared__ int s_t;
    __syncthreads();
    if (threadIdx.x == 0) {
        unsigned a = atomicAdd(&g_wctr[s], 1u);
        unsigned m = a % (unsigned)(n + NCTA);
        s_t = (m < (unsigned)n) ? (int)m : -1;
    }
    __syncthreads();
    return s_t;
}

// ---------------- bf16 cp.async GEMM tile: 32x64, 4 warps --------------------
template<int ACT, int CBF16>
__device__ __forceinline__ void gemm32_tile(
    uint32_t* sm,
    const __nv_bfloat16* __restrict__ A_t, const __nv_bfloat16* __restrict__ W,
    const float* __restrict__ bias, void* Cv,
    int N, int K, int row0, int col0)
{
    const int t = threadIdx.x;
    const int lane = t & 31, wn = t >> 5;
    const int g = lane >> 2, tig = lane & 3;
    const int ar = t >> 2, ac = (t & 3) * 8;
    const int ntiles = K >> 5;
    const uint32_t sbase = (uint32_t)__cvta_generic_to_shared(sm);
    const uint32_t aoff = (uint32_t)(ar * SROW + (t & 3) * 4) * 4u;

    const __nv_bfloat16* Ap  = A_t + (size_t)ar * K + ac;
    const __nv_bfloat16* Wp0 = W + (size_t)(col0 + ar) * K + ac;
    const __nv_bfloat16* Wp1 = W + (size_t)(col0 + ar + 32) * K + ac;

    cpa16(sbase + aoff, Ap);
    cpa16(sbase + A32W * 4 + aoff, Wp0);
    cpa16(sbase + (A32W + 32 * SROW) * 4 + aoff, Wp1);
    CP_COMMIT();

    float c[2][2][4] = {};

    for (int kt = 0; kt < ntiles; kt++) {
        if (kt + 1 < ntiles) {
            uint32_t nb = sbase + (((kt + 1) & 1) * GSTAGE) * 4 + aoff;
            cpa16(nb, Ap + (kt + 1) * 32);
            cpa16(nb + A32W * 4, Wp0 + (kt + 1) * 32);
            cpa16(nb + (A32W + 32 * SROW) * 4, Wp1 + (kt + 1) * 32);
        }
        CP_COMMIT();
        CP_WAIT1();
        __syncthreads();
        uint32_t* As = sm + (kt & 1) * GSTAGE;
        uint32_t* Bs = As + A32W;
        #pragma unroll
        for (int k16 = 0; k16 < 2; k16++) {
            const int kb = k16 * 8;
            uint32_t afr[2][4], bfr[2][2];
            #pragma unroll
            for (int mi = 0; mi < 2; mi++) {
                int r = mi * 16 + g;
                afr[mi][0] = As[r * SROW + kb + tig];
                afr[mi][1] = As[(r + 8) * SROW + kb + tig];
                afr[mi][2] = As[r * SROW + kb + tig + 4];
                afr[mi][3] = As[(r + 8) * SROW + kb + tig + 4];
            }
            #pragma unroll
            for (int ni = 0; ni < 2; ni++) {
                int n = wn * 16 + ni * 8 + g;
                bfr[ni][0] = Bs[n * SROW + kb + tig];
                bfr[ni][1] = Bs[n * SROW + kb + tig + 4];
            }
            #pragma unroll
            for (int mi = 0; mi < 2; mi++)
                #pragma unroll
                for (int ni = 0; ni < 2; ni++)
                    mma_bf16(c[mi][ni], afr[mi][0], afr[mi][1], afr[mi][2],
                             afr[mi][3], bfr[ni][0], bfr[ni][1]);
        }
        __syncthreads();
    }

    #pragma unroll
    for (int mi = 0; mi < 2; mi++) {
        int r = row0 + mi * 16 + g;
        #pragma unroll
        for (int ni = 0; ni < 2; ni++) {
            int n = col0 + wn * 16 + ni * 8 + 2 * tig;
            float b0 = bias[n], b1 = bias[n + 1];
            float v0 = c[mi][ni][0] + b0, v1 = c[mi][ni][1] + b1;
            float v2 = c[mi][ni][2] + b0, v3 = c[mi][ni][3] + b1;
            if (ACT == 1) { v0 = silu_f(v0); v1 = silu_f(v1); v2 = silu_f(v2); v3 = silu_f(v3); }
            else if (ACT == 2) { v0 = softplus_f(v0); v1 = softplus_f(v1); v2 = softplus_f(v2); v3 = softplus_f(v3); }
            if (CBF16) {
                __nv_bfloat16* Cb = (__nv_bfloat16*)Cv;
                *(uint32_t*)(Cb + (size_t)r * N + n) = pk(v0, v1);
                *(uint32_t*)(Cb + (size_t)(r + 8) * N + n) = pk(v2, v3);
            } else {
                float* Cf = (float*)Cv;
                *(float2*)&Cf[(size_t)r * N + n] = make_float2(v0, v1);
                *(float2*)&Cf[(size_t)(r + 8) * N + n] = make_float2(v2, v3);
            }
        }
    }
}

// ---------------- conv tile (h-tile=4, both channels), 128 threads -----------
__device__ __forceinline__ void conv_tile(
    uint32_t* dsmw, int bid, const float* __restrict__ cw,
    const float* __restrict__ cb)
{
    float* rows = (float*)dsmw;           // [2][6][520]
    __shared__ float wsh[36];
    __shared__ float bsh[2];
    const int T = bid >> 6;
    const int h0 = (bid & 63) * 4;
    const int t = threadIdx.x;
    if (t < 36) wsh[t] = cw[t];
    if (t < 2) bsh[t] = cb[t];
    const __nv_bfloat16* Pb = g_Pbf + (size_t)T * HROWS * D2;

    for (int idx = t; idx < 2 * 6 * 64; idx += 128) {
        int i = idx / 384;
        int rem = idx - i * 384;
        int r = rem >> 6;
        int c8 = rem & 63;
        int hh = h0 + r - 1;
        float4 f0 = make_float4(0.f, 0.f, 0.f, 0.f), f1 = f0;
        if (hh >= 0 && hh < Lh) {
            uint4 q = *(const uint4*)(Pb + (size_t)(i * Lh + hh) * D2 + c8 * 8);
            const __nv_bfloat162* h = (const __nv_bfloat162*)&q;
            float2 a0 = __bfloat1622float2(h[0]), a1 = __bfloat1622float2(h[1]);
            float2 a2 = __bfloat1622float2(h[2]), a3 = __bfloat1622float2(h[3]);
            f0 = make_float4(a0.x, a0.y, a1.x, a1.y);
            f1 = make_float4(a2.x, a2.y, a3.x, a3.y);
        }
        *(float4*)&rows[(i * 6 + r) * 520 + c8 * 8] = f0;
        *(float4*)&rows[(i * 6 + r) * 520 + c8 * 8 + 4] = f1;
    }
    __syncthreads();

    #pragma unroll
    for (int oh = 0; oh < 4; oh++) {
        #pragma unroll
        for (int ws = 0; ws < 4; ws++) {
            int w = t + ws * 128;
            float acc0 = bsh[0], acc1 = bsh[1];
            #pragma unroll
            for (int i = 0; i < 2; i++)
                #pragma unroll
                for (int kh = 0; kh < 3; kh++) {
                    const float* rp = &rows[(i * 6 + oh + kh) * 520];
                    float dl = (w == 0)      ? 0.f : rp[w - 1];
                    float dc = rp[w];
                    float dr = (w == D2 - 1) ? 0.f : rp[w + 1];
                    acc0 += dl * wsh[i * 9 + kh * 3 + 0]
                          + dc * wsh[i * 9 + kh * 3 + 1]
                          + dr * wsh[i * 9 + kh * 3 + 2];
                    acc1 += dl * wsh[18 + i * 9 + kh * 3 + 0]
                          + dc * wsh[18 + i * 9 + kh * 3 + 1]
                          + dr * wsh[18 + i * 9 + kh * 3 + 2];
                }
            int h = h0 + oh;
            g_XCbf[((size_t)T * HROWS + 0 * Lh + h) * D2 + w] = __float2bfloat16(silu_f(acc0));
            g_XCbf[((size_t)T * HROWS + 1 * Lh + h) * D2 + w] = __float2bfloat16(silu_f(acc1));
        }
    }
    __syncthreads();
}

// ---------------- SSM tile: 4-slab GEMM + S2 + Horner + silu -----------------
__device__ __forceinline__ void ssm_tile(uint32_t* dsm, int tile)
{
    const int t = threadIdx.x;
    const int lane = t & 31, wn = t >> 5;
    const int g = lane >> 2, tig = lane & 3;
    const int row0 = (tile >> 3) * 32, col0 = (tile & 7) * 64;
    const int ar = t >> 2, ac = (t & 3) * 8;
    const uint32_t sbase = (uint32_t)__cvta_generic_to_shared(dsm);
    const uint32_t aoff = (uint32_t)(ar * SROW + (t & 3) * 4) * 4u;
    float* s2s = (float*)(dsm + 2 * SSTAGE);

    const __nv_bfloat16* Ap = g_BMbf + (size_t)(row0 + ar) * Sn + ac;

    {
        uint32_t sb = sbase + aoff;
        cpa16(sb, Ap);
        #pragma unroll
        for (int j = 0; j < 4; j++) {
            uint32_t eb = sb + (A32W + j * B64W) * 4;
            cpa16(eb, g_Ebf + (size_t)(j * D2 + col0 + ar) * Sn + ac);
            cpa16(eb + 32 * SROW * 4,
                  g_Ebf + (size_t)(j * D2 + col0 + ar + 32) * Sn + ac);
        }
    }
    CP_COMMIT();

    // per-row sum of Bm^2 (deterministic shuffle reduce: 4 lanes per row)
    float s2p = 0.f;
    {
        const uint4* bm = (const uint4*)(g_BMbf + (size_t)(row0 + (t >> 2)) * Sn
                                         + (t & 3) * 32);
        #pragma unroll
        for (int i = 0; i < 4; i++) {
            uint4 q = bm[i];
            const __nv_bfloat162* h = (const __nv_bfloat162*)&q;
            #pragma unroll
            for (int p = 0; p < 4; p++) {
                float2 f = __bfloat1622float2(h[p]);
                s2p += f.x * f.x + f.y * f.y;
            }
        }
    }
    s2p += __shfl_xor_sync(0xffffffffu, s2p, 1);
    s2p += __shfl_xor_sync(0xffffffffu, s2p, 2);
    if ((t & 3) == 0) s2s[t >> 2] = s2p;

    float c[4][2][2][4] = {};

    for (int kt = 0; kt < 4; kt++) {
        if (kt + 1 < 4) {
            uint32_t sb = sbase + (((kt + 1) & 1) * SSTAGE) * 4 + aoff;
            cpa16(sb, Ap + (kt + 1) * 32);
            #pragma unroll
            for (int j = 0; j < 4; j++) {
                uint32_t eb = sb + (A32W + j * B64W) * 4;
                cpa16(eb, g_Ebf + (size_t)(j * D2 + col0 + ar) * Sn + (kt + 1) * 32 + ac);
                cpa16(eb + 32 * SROW * 4,
                      g_Ebf + (size_t)(j * D2 + col0 + ar + 32) * Sn + (kt + 1) * 32 + ac);
            }
        }
        CP_COMMIT();
        CP_WAIT1();
        __syncthreads();
        uint32_t* As = dsm + (kt & 1) * SSTAGE;
        #pragma unroll
        for (int k16 = 0; k16 < 2; k16++) {
            const int kb = k16 * 8;
            uint32_t afr[2][4];
            #pragma unroll
            for (int mi = 0; mi < 2; mi++) {
                int r = mi * 16 + g;
                afr[mi][0] = As[r * SROW + kb + tig];
                afr[mi][1] = As[(r + 8) * SROW + kb + tig];
                afr[mi][2] = As[r * SROW + kb + tig + 4];
                afr[mi][3] = As[(r + 8) * SROW + kb + tig + 4];
            }
            #pragma unroll
            for (int j = 0; j < 4; j++) {
                const uint32_t* Es = As + A32W + j * B64W;
                uint32_t bfr[2][2];
                #pragma unroll
                for (int ni = 0; ni < 2; ni++) {
                    int n = wn * 16 + ni * 8 + g;
                    bfr[ni][0] = Es[n * SROW + kb + tig];
                    bfr[ni][1] = Es[n * SROW + kb + tig + 4];
                }
                #pragma unroll
                for (int mi = 0; mi < 2; mi++)
                    #pragma unroll
                    for (int ni = 0; ni < 2; ni++)
                        mma_bf16(c[j][mi][ni], afr[mi][0], afr[mi][1], afr[mi][2],
                                 afr[mi][3], bfr[ni][0], bfr[ni][1]);
            }
        }
        __syncthreads();
    }

    #pragma unroll
    for (int mi = 0; mi < 2; mi++) {
        #pragma unroll
        for (int half = 0; half < 2; half++) {
            int rl = mi * 16 + g + half * 8;
            int r = row0 + rl;
            float s2 = s2s[rl];
            #pragma unroll
            for (int ni = 0; ni < 2; ni++) {
                int d = col0 + wn * 16 + ni * 8 + 2 * tig;
                float2 dl = *(const float2*)&g_DELTA[(size_t)r * D2 + d];
                float2 xc = __bfloat1622float2(
                    *(const __nv_bfloat162*)(g_XCbf + (size_t)r * D2 + d));
                int q0 = half * 2;
                float u0 = dl.x - LN2F, u1 = dl.y - LN2F;
                float s0 = c[0][mi][ni][q0]
                         + u0 * (c[1][mi][ni][q0] + u0 * (c[2][mi][ni][q0] + u0 * c[3][mi][ni][q0]));
                float s1 = c[0][mi][ni][q0 + 1]
                         + u1 * (c[1][mi][ni][q0 + 1] + u1 * (c[2][mi][ni][q0 + 1] + u1 * c[3][mi][ni][q0 + 1]));
                s0 += xc.x * dl.x * s2;
                s1 += xc.y * dl.y * s2;
                *(float2*)&g_XS[(size_t)r * D2 + d] = make_float2(silu_f(s0), silu_f(s1));
            }
        }
    }
}

// ---------------- out tile: comb fused, register-staged fp32->bf16 -----------
__device__ __forceinline__ void out_tile(
    uint32_t* smbuf, int tile,
    const float* __restrict__ out_W, const float* __restrict__ out_b,
    float* __restrict__ out)
{
    uint32_t* As = smbuf;
    uint32_t* Bs = smbuf + A32W;
    const int t = threadIdx.x;
    const int lane = t & 31, wn = t >> 5;
    const int g = lane >> 2, tig = lane & 3;
    const int row0 = (tile >> 2) * 32, col0 = (tile & 3) * 64;
    const int ar = t >> 2, ac = (t & 3) * 8;
    const int N = Dm, K = D2;

    const float* Ap  = g_XS + (size_t)(row0 + ar) * K + ac;
    const float* A2p = g_XS + (size_t)(HROWS + row0 + ar) * K + ac;
    const float* A3p = g_RES + (size_t)(row0 + ar) * K + ac;
    const float* Wp0 = out_W + (size_t)(col0 + ar) * K + ac;
    const float* Wp1 = out_W + (size_t)(col0 + ar + 32) * K + ac;

    float c[2][2][4] = {};
    const int ntiles = K >> 5;
    uint4 ab, wb0, wb1;

#define LOAD_AB(ko) do { \
    float4 u = *(const float4*)(Ap + (ko)); \
    float4 v = *(const float4*)(Ap + (ko) + 4); \
    float4 u2 = *(const float4*)(A2p + (ko)), u3 = *(const float4*)(A3p + (ko)); \
    float4 v2 = *(const float4*)(A2p + (ko) + 4), v3 = *(const float4*)(A3p + (ko) + 4); \
    u.x = (u.x + u2.x) * u3.x; u.y = (u.y + u2.y) * u3.y; \
    u.z = (u.z + u2.z) * u3.z; u.w = (u.w + u2.w) * u3.w; \
    v.x = (v.x + v2.x) * v3.x; v.y = (v.y + v2.y) * v3.y; \
    v.z = (v.z + v2.z) * v3.z; v.w = (v.w + v2.w) * v3.w; \
    ab = pack8(u, v); \
    { float4 xx = *(const float4*)(Wp0 + (ko)); \
      float4 yy = *(const float4*)(Wp0 + (ko) + 4); \
      wb0 = pack8(xx, yy); } \
    { float4 xx = *(const float4*)(Wp1 + (ko)); \
      float4 yy = *(const float4*)(Wp1 + (ko) + 4); \
      wb1 = pack8(xx, yy); } \
} while (0)

    LOAD_AB(0);
    for (int kt = 0; kt < ntiles; kt++) {
        __syncthreads();
        *(uint4*)&As[ar * SROW + (t & 3) * 4] = ab;
        *(uint4*)&Bs[ar * SROW + (t & 3) * 4] = wb0;
        *(uint4*)&Bs[(ar + 32) * SROW + (t & 3) * 4] = wb1;
        __syncthreads();
        if (kt + 1 < ntiles) LOAD_AB((kt + 1) * 32);
        #pragma unroll
        for (int k16 = 0; k16 < 2; k16++) {
            const int kb = k16 * 8;
            uint32_t afr[2][4], bfr[2][2];
            #pragma unroll
            for (int mi = 0; mi < 2; mi++) {
                int r = mi * 16 + g;
                afr[mi][0] = As[r * SROW + kb + tig];
                afr[mi][1] = As[(r + 8) * SROW + kb + tig];
                afr[mi][2] = As[r * SROW + kb + tig + 4];
                afr[mi][3] = As[(r + 8) * SROW + kb + tig + 4];
            }
            #pragma unroll
            for (int ni = 0; ni < 2; ni++) {
                int n = wn * 16 + ni * 8 + g;
                bfr[ni][0] = Bs[n * SROW + kb + tig];
                bfr[ni][1] = Bs[n * SROW + kb + tig + 4];
            }
            #pragma unroll
            for (int mi = 0; mi < 2; mi++)
                #pragma unroll
                for (int ni = 0; ni < 2; ni++)
                    mma_bf16(c[mi][ni], afr[mi][0], afr[mi][1], afr[mi][2],
                             afr[mi][3], bfr[ni][0], bfr[ni][1]);
        }
    }
#undef LOAD_AB

    #pragma unroll
    for (int mi = 0; mi < 2; mi++) {
        int r = row0 + mi * 16 + g;
        #pragma unroll
        for (int ni = 0; ni < 2; ni++) {
            int n = col0 + wn * 16 + ni * 8 + 2 * tig;
            float b0 = out_b[n], b1 = out_b[n + 1];
            *(float2*)&out[(size_t)r * N + n] =
                make_float2(c[mi][ni][0] + b0, c[mi][ni][1] + b1);
            *(float2*)&out[(size_t)(r + 8) * N + n] =
                make_float2(c[mi][ni][2] + b0, c[mi][ni][3] + b1);
        }
    }
    __syncthreads();
}

// ---------------- the persistent fused kernel --------------------------------
__global__ void __launch_bounds__(128, 2) fused_kernel(
    const float* __restrict__ x, const float* __restrict__ mouth,
    const float* __restrict__ norm_w,
    const float* __restrict__ inp_W, const float* __restrict__ inp_b,
    const float* __restrict__ out_W, const float* __restrict__ out_b,
    const float* __restrict__ Dlin_W, const float* __restrict__ Dlin_b,
    const float* __restrict__ conv_W, const float* __restrict__ conv_b,
    const float* __restrict__ fc1_W, const float* __restrict__ fc1_b,
    const float* __restrict__ fc2_W, const float* __restrict__ fc2_b,
    const float* __restrict__ A, float* __restrict__ out)
{
    extern __shared__ uint32_t dsm[];
    const int cta = blockIdx.x, t = threadIdx.x;
    int tile;

    // ---- S0: prep (static partition, uniform work) ----
    {
        int warp = t >> 5, lane = t & 31;
        int r = cta * 4 + warp;
        if (r < NROWS && cta < 256) {
            const float* src = (r < HROWS) ? (x + (size_t)r * Dm)
                                           : (mouth + (size_t)(r - HROWS) * Dm);
            float4 v0 = ((const float4*)src)[lane * 2];
            float4 v1 = ((const float4*)src)[lane * 2 + 1];
            float s = v0.x * v0.x + v0.y * v0.y + v0.z * v0.z + v0.w * v0.w
                    + v1.x * v1.x + v1.y * v1.y + v1.z * v1.z + v1.w * v1.w;
            #pragma unroll
            for (int o = 16; o; o >>= 1) s += __shfl_xor_sync(0xffffffffu, s, o);
            float rinv = 1.f / sqrtf(s + 1e-5f);
            float4 w0 = ((const float4*)norm_w)[lane * 2];
            float4 w1 = ((const float4*)norm_w)[lane * 2 + 1];
            v0.x *= rinv * w0.x; v0.y *= rinv * w0.y; v0.z *= rinv * w0.z; v0.w *= rinv * w0.w;
            v1.x *= rinv * w1.x; v1.y *= rinv * w1.y; v1.z *= rinv * w1.z; v1.w *= rinv * w1.w;
            *(uint4*)(g_XNbf + (size_t)r * Dm + lane * 8) = pack8(v0, v1);
        }
        for (int idx = cta * 128 + t; idx < D2 * Sn; idx += NCTA * 128) {
            float a = A[idx];
            float e0 = exp2f(a);
            g_Ebf[0 * D2 * Sn + idx] = __float2bfloat16(e0);
            g_Ebf[1 * D2 * Sn + idx] = __float2bfloat16(a * e0);
            g_Ebf[2 * D2 * Sn + idx] = __float2bfloat16(0.5f * a * a * e0);
            g_Ebf[3 * D2 * Sn + idx] = __float2bfloat16((1.f / 6.f) * a * a * a * e0);
        }
        // weights: 73728 float8-chunks total
        for (int v8 = cta * 128 + t; v8 < 73728; v8 += NCTA * 128) {
            const float* src; __nv_bfloat16* dst; int off;
            if (v8 < 16384)      { src = inp_W;  dst = g_Wibf; off = v8; }
            else if (v8 < 32768) { src = Dlin_W; dst = g_Wdbf; off = v8 - 16384; }
            else if (v8 < 65536) { src = fc1_W;  dst = g_W1bf; off = v8 - 32768; }
            else                 { src = fc2_W;  dst = g_W2bf; off = v8 - 65536; }
            int idx = off * 8;
            float4 u = ((const float4*)(src + idx))[0];
            float4 w = ((const float4*)(src + idx))[1];
            *(uint4*)(dst + idx) = pack8(u, w);
        }
    }
    grid_barrier(0);

    // ---- S1: inp GEMM (256 tiles) + res GEMM (128 tiles) ----
    while ((tile = grab_tile(1, 384)) >= 0) {
        if (tile < 256) {
            int row0 = (tile >> 3) * 32, col0 = (tile & 7) * 64;
            gemm32_tile<0, 1>(dsm, g_XNbf + (size_t)row0 * Dm, g_Wibf,
                              inp_b, g_Pbf, D2, Dm, row0, col0);
        } else {
            int b2 = tile - 256;
            int row0 = (b2 >> 3) * 32, col0 = (b2 & 7) * 64;
            gemm32_tile<1, 0>(dsm, g_XNbf + (size_t)row0 * Dm, g_Wdbf,
                              Dlin_b, g_RES, D2, Dm, row0, col0);
        }
    }
    grid_barrier(1);

    // ---- S2: conv (128 tiles) ----
    while ((tile = grab_tile(2, 128)) >= 0)
        conv_tile(dsm, tile, conv_W, conv_b);
    grid_barrier(2);

    // ---- S3: delta GEMM (256) + Bm GEMM (64) ----
    while ((tile = grab_tile(3, 320)) >= 0) {
        if (tile < 256) {
            int row0 = (tile >> 3) * 32, col0 = (tile & 7) * 64;
            gemm32_tile<2, 0>(dsm, g_XCbf + (size_t)row0 * D2, g_W1bf,
                              fc1_b, g_DELTA, D2, D2, row0, col0);
        } else {
            int b2 = tile - 256;
            int row0 = (b2 >> 1) * 32, col0 = (b2 & 1) * 64;
            gemm32_tile<0, 1>(dsm, g_XCbf + (size_t)row0 * D2, g_W2bf,
                              fc2_b, g_BMbf, Sn, D2, row0, col0);
        }
    }
    grid_barrier(3);

    // ---- S4: ssm (256 tiles) ----
    while ((tile = grab_tile(4, 256)) >= 0)
        ssm_tile(dsm, tile);
    grid_barrier(4);

    // ---- S5: out (64 tiles) ----
    while ((tile = grab_tile(5, 64)) >= 0)
        out_tile(dsm, tile, out_W, out_b, out);
}

// ---------------- launch ----------------
extern "C" void kernel_launch(void* const* d_in, const int* in_sizes, int n_in,
                              void* d_out, int out_size)
{
    const float* x      = (const float*)d_in[0];
    const float* mouth  = (const float*)d_in[1];
    const float* norm_w = (const float*)d_in[2];
    const float* inp_W  = (const float*)d_in[3];
    const float* inp_b  = (const float*)d_in[4];
    const float* out_W  = (const float*)d_in[5];
    const float* out_b  = (const float*)d_in[6];
    const float* Dlin_W = (const float*)d_in[7];
    const float* Dlin_b = (const float*)d_in[8];
    const float* conv_W = (const float*)d_in[9];
    const float* conv_b = (const float*)d_in[10];
    const float* fc1_W  = (const float*)d_in[11];
    const float* fc1_b  = (const float*)d_in[12];
    const float* fc2_W  = (const float*)d_in[13];
    const float* fc2_b  = (const float*)d_in[14];
    const float* A      = (const float*)d_in[15];

    const int SMEM = 2 * SSTAGE * 4 + 128;   // 46208 B (ssm stages + s2s)
    static int configured = 0;
    if (!configured) {
        cudaFuncSetAttribute(fused_kernel,
                             cudaFuncAttributeMaxDynamicSharedMemorySize, SMEM);
        configured = 1;
    }

    fused_kernel<<<NCTA, 128, SMEM>>>(
        x, mouth, norm_w, inp_W, inp_b, out_W, out_b, Dlin_W, Dlin_b,
        conv_W, conv_b, fc1_W, fc1_b, fc2_W, fc2_b, A, (float*)d_out);
}

// round 15
// speedup vs baseline: 1.7772x; 1.7772x over previous
#include <cuda_runtime.h>
#include <cuda_bf16.h>
#include <math.h>
#include <stdint.h>

// Problem constants
#define Dm     256
#define D2     512
#define Sn     128
#define Lh     256
#define NROWS  1024
#define HROWS  512
#define LN2F   0.69314718055994531f

// BK=64 tile geometry (words = uint32)
#define SR64   36                  // row stride: 32 data words (64 bf16) + 4 pad
#define AW64   (32 * SR64)         // 32x64 bf16 A tile
#define BW64   (64 * SR64)         // 64x64 bf16 B tile
#define GST64  (AW64 + BW64)       // gemm stage words
#define SST64  (AW64 + 4 * BW64)   // ssm stage words

// BK=32 constants (out kernel only)
#define OSROW  20
#define OA32W  (32 * OSROW)
#define OB64W  (64 * OSROW)

// ---------------- scratch ----------------
__device__ __nv_bfloat16 g_XNbf[NROWS * Dm];
__device__ __nv_bfloat16 g_Wibf[D2 * Dm];
__device__ __nv_bfloat16 g_Wdbf[D2 * Dm];
__device__ __nv_bfloat16 g_W1bf[D2 * D2];
__device__ __nv_bfloat16 g_W2bf[Sn * D2];
__device__ __nv_bfloat16 g_Pbf[NROWS * D2];
__device__ __nv_bfloat16 g_XCbf[NROWS * D2];
__device__ float         g_DELTA[NROWS * D2];
__device__ __nv_bfloat16 g_BMbf[NROWS * Sn];
__device__ __nv_bfloat16 g_Ebf[4 * D2 * Sn];
__device__ float         g_XS[NROWS * D2];
__device__ float         g_RES[HROWS * D2];

__device__ __forceinline__ float silu_f(float v) { return v / (1.f + expf(-v)); }
__device__ __forceinline__ float softplus_f(float v) {
    return fmaxf(v, 0.f) + log1pf(expf(-fabsf(v)));
}
__device__ __forceinline__ uint32_t pk(float a, float b) {
    __nv_bfloat162 h = __floats2bfloat162_rn(a, b);
    return *reinterpret_cast<uint32_t*>(&h);
}
__device__ __forceinline__ uint4 pack8(float4 u, float4 v) {
    return make_uint4(pk(u.x, u.y), pk(u.z, u.w), pk(v.x, v.y), pk(v.z, v.w));
}
__device__ __forceinline__ void mma_bf16(float c[4],
    uint32_t a0, uint32_t a1, uint32_t a2, uint32_t a3,
    uint32_t b0, uint32_t b1)
{
    asm("mma.sync.aligned.m16n8k16.row.col.f32.bf16.bf16.f32 "
        "{%0,%1,%2,%3}, {%4,%5,%6,%7}, {%8,%9}, {%0,%1,%2,%3};"
        : "+f"(c[0]), "+f"(c[1]), "+f"(c[2]), "+f"(c[3])
        : "r"(a0), "r"(a1), "r"(a2), "r"(a3), "r"(b0), "r"(b1));
}
__device__ __forceinline__ void ldsm_x4(uint32_t& r0, uint32_t& r1,
                                        uint32_t& r2, uint32_t& r3, uint32_t addr)
{
    asm volatile("ldmatrix.sync.aligned.m8n8.x4.shared.b16 {%0,%1,%2,%3}, [%4];"
                 : "=r"(r0), "=r"(r1), "=r"(r2), "=r"(r3) : "r"(addr));
}
__device__ __forceinline__ void cpa16(uint32_t saddr, const void* g) {
    asm volatile("cp.async.ca.shared.global [%0], [%1], 16;"
                 :: "r"(saddr), "l"(g) : "memory");
}
#define CP_COMMIT() asm volatile("cp.async.commit_group;" ::: "memory")
#define CP_WAIT1()  asm volatile("cp.async.wait_group 1;" ::: "memory")

// ---------------- prep: XNbf + E slabs + weight->bf16 ------------------------
__global__ __launch_bounds__(256) void prep_kernel(
    const float* __restrict__ x, const float* __restrict__ mouth,
    const float* __restrict__ norm_w, const float* __restrict__ A,
    const float* __restrict__ inp_W, const float* __restrict__ Dlin_W,
    const float* __restrict__ fc1_W, const float* __restrict__ fc2_W)
{
    const int bid = blockIdx.x, t = threadIdx.x;
    if (bid < 128) {
        int warp = t >> 5, lane = t & 31;
        int r = bid * 8 + warp;
        const float* src = (r < HROWS) ? (x + (size_t)r * Dm)
                                       : (mouth + (size_t)(r - HROWS) * Dm);
        float4 v0 = ((const float4*)src)[lane * 2];
        float4 v1 = ((const float4*)src)[lane * 2 + 1];
        float s = v0.x * v0.x + v0.y * v0.y + v0.z * v0.z + v0.w * v0.w
                + v1.x * v1.x + v1.y * v1.y + v1.z * v1.z + v1.w * v1.w;
        #pragma unroll
        for (int o = 16; o; o >>= 1) s += __shfl_xor_sync(0xffffffffu, s, o);
        float rinv = 1.f / sqrtf(s + 1e-5f);
        float4 w0 = ((const float4*)norm_w)[lane * 2];
        float4 w1 = ((const float4*)norm_w)[lane * 2 + 1];
        v0.x *= rinv * w0.x; v0.y *= rinv * w0.y; v0.z *= rinv * w0.z; v0.w *= rinv * w0.w;
        v1.x *= rinv * w1.x; v1.y *= rinv * w1.y; v1.z *= rinv * w1.z; v1.w *= rinv * w1.w;
        *(uint4*)(g_XNbf + (size_t)r * Dm + lane * 8) = pack8(v0, v1);
    } else if (bid < 384) {
        int idx = (bid - 128) * 256 + t;   // d*128 + n
        float a = A[idx];
        float e0 = exp2f(a);               // exp(ln2 * a)
        g_Ebf[0 * D2 * Sn + idx] = __float2bfloat16(e0);
        g_Ebf[1 * D2 * Sn + idx] = __float2bfloat16(a * e0);
        g_Ebf[2 * D2 * Sn + idx] = __float2bfloat16(0.5f * a * a * e0);
        g_Ebf[3 * D2 * Sn + idx] = __float2bfloat16((1.f / 6.f) * a * a * a * e0);
    } else {
        int wb = bid - 384;                // 0..287
        const float* src; __nv_bfloat16* dst; int base;
        if (wb < 64)       { src = inp_W;  dst = g_Wibf; base = wb * 2048; }
        else if (wb < 128) { src = Dlin_W; dst = g_Wdbf; base = (wb - 64) * 2048; }
        else if (wb < 256) { src = fc1_W;  dst = g_W1bf; base = (wb - 128) * 2048; }
        else               { src = fc2_W;  dst = g_W2bf; base = (wb - 256) * 2048; }
        int idx = base + t * 8;
        float4 u = ((const float4*)(src + idx))[0];
        float4 v = ((const float4*)(src + idx))[1];
        *(uint4*)(dst + idx) = pack8(u, v);
    }
}

// ---------------- BK=64 bf16 GEMM core: 32x64 tile, 4 warps, ldmatrix --------
// C = A[32 x K] @ W[N x K]^T + bias. 2-stage cp.async, m16n8k16.
template<int ACT, int CBF16>
__device__ __forceinline__ void gemm64_tile(
    uint32_t* sm,
    const __nv_bfloat16* __restrict__ A_t, const __nv_bfloat16* __restrict__ W,
    const float* __restrict__ bias, void* Cv,
    int N, int K, int row0, int col0)
{
    const int t = threadIdx.x;
    const int lane = t & 31, wn = t >> 5;
    const int g = lane >> 2, tig = lane & 3;
    const int ntk = K >> 6;
    const uint32_t sbase = (uint32_t)__cvta_generic_to_shared(sm);

    // cp.async mapping: A 256 chunks (2/thread), B 512 chunks (4/thread)
    const __nv_bfloat16* Agp[2]; uint32_t Aso[2];
    #pragma unroll
    for (int i = 0; i < 2; i++) {
        int c = t + i * 128, row = c >> 3, cw = c & 7;
        Agp[i] = A_t + (size_t)row * K + cw * 8;
        Aso[i] = (uint32_t)(row * SR64 + cw * 4) * 4u;
    }
    const __nv_bfloat16* Wgp[4]; uint32_t Wso[4];
    #pragma unroll
    for (int i = 0; i < 4; i++) {
        int c = t + i * 128, row = c >> 3, cw = c & 7;
        Wgp[i] = W + (size_t)(col0 + row) * K + cw * 8;
        Wso[i] = (uint32_t)(AW64 + row * SR64 + cw * 4) * 4u;
    }

    // prologue stage 0
    #pragma unroll
    for (int i = 0; i < 2; i++) cpa16(sbase + Aso[i], Agp[i]);
    #pragma unroll
    for (int i = 0; i < 4; i++) cpa16(sbase + Wso[i], Wgp[i]);
    CP_COMMIT();

    // ldmatrix lane addressing
    const int mM = lane >> 3;
    const int rA = ((mM & 1) << 3) + (lane & 7);
    const uint32_t cbB = (uint32_t)((mM >> 1) * 16);

    float c[2][2][4] = {};

    for (int kt = 0; kt < ntk; kt++) {
        if (kt + 1 < ntk) {
            uint32_t nb = sbase + (uint32_t)(((kt + 1) & 1) * GST64) * 4u;
            int ko = (kt + 1) * 64;
            #pragma unroll
            for (int i = 0; i < 2; i++) cpa16(nb + Aso[i], Agp[i] + ko);
            #pragma unroll
            for (int i = 0; i < 4; i++) cpa16(nb + Wso[i], Wgp[i] + ko);
        }
        CP_COMMIT();
        CP_WAIT1();
        __syncthreads();
        uint32_t sa = sbase + (uint32_t)((kt & 1) * GST64) * 4u;
        uint32_t sb = sa + (uint32_t)AW64 * 4u;
        #pragma unroll
        for (int k16 = 0; k16 < 4; k16++) {
            uint32_t off = (uint32_t)(k16 * 32) + cbB;
            uint32_t afr[2][4], b0, b1, b2, b3;
            ldsm_x4(afr[0][0], afr[0][1], afr[0][2], afr[0][3],
                    sa + (uint32_t)(rA * SR64) * 4u + off);
            ldsm_x4(afr[1][0], afr[1][1], afr[1][2], afr[1][3],
                    sa + (uint32_t)((16 + rA) * SR64) * 4u + off);
            ldsm_x4(b0, b1, b2, b3,
                    sb + (uint32_t)((wn * 16 + rA) * SR64) * 4u + off);
            #pragma unroll
            for (int mi = 0; mi < 2; mi++) {
                mma_bf16(c[mi][0], afr[mi][0], afr[mi][1], afr[mi][2], afr[mi][3], b0, b2);
                mma_bf16(c[mi][1], afr[mi][0], afr[mi][1], afr[mi][2], afr[mi][3], b1, b3);
            }
        }
        __syncthreads();
    }

    #pragma unroll
    for (int mi = 0; mi < 2; mi++) {
        int r = row0 + mi * 16 + g;
        #pragma unroll
        for (int ni = 0; ni < 2; ni++) {
            int n = col0 + wn * 16 + ni * 8 + 2 * tig;
            float b0 = bias[n], b1 = bias[n + 1];
            float v0 = c[mi][ni][0] + b0, v1 = c[mi][ni][1] + b1;
            float v2 = c[mi][ni][2] + b0, v3 = c[mi][ni][3] + b1;
            if (ACT == 1) { v0 = silu_f(v0); v1 = silu_f(v1); v2 = silu_f(v2); v3 = silu_f(v3); }
            else if (ACT == 2) { v0 = softplus_f(v0); v1 = softplus_f(v1); v2 = softplus_f(v2); v3 = softplus_f(v3); }
            if (CBF16) {
                __nv_bfloat16* Cb = (__nv_bfloat16*)Cv;
                *(uint32_t*)(Cb + (size_t)r * N + n) = pk(v0, v1);
                *(uint32_t*)(Cb + (size_t)(r + 8) * N + n) = pk(v2, v3);
            } else {
                float* Cf = (float*)Cv;
                *(float2*)&Cf[(size_t)r * N + n] = make_float2(v0, v1);
                *(float2*)&Cf[(size_t)(r + 8) * N + n] = make_float2(v2, v3);
            }
        }
    }
}

// ---------------- mega1: inp GEMM (0..255) + res GEMM (256..383) -------------
__global__ __launch_bounds__(128) void mega1_kernel(
    const float* __restrict__ inp_b, const float* __restrict__ Dlin_b)
{
    __shared__ uint32_t sm[2 * GST64];
    const int bid = blockIdx.x;
    if (bid < 256) {
        int row0 = (bid >> 3) * 32, col0 = (bid & 7) * 64;
        gemm64_tile<0, 1>(sm, g_XNbf + (size_t)row0 * Dm, g_Wibf,
                          inp_b, g_Pbf, D2, Dm, row0, col0);
    } else {
        int b2 = bid - 256;
        int row0 = (b2 >> 3) * 32, col0 = (b2 & 7) * 64;
        gemm64_tile<1, 0>(sm, g_XNbf + (size_t)row0 * Dm, g_Wdbf,
                          Dlin_b, g_RES, D2, Dm, row0, col0);
    }
}

// ---------------- conv 3x3 SAME + silu, h-tile = 4, bf16 in/out --------------
__global__ __launch_bounds__(256) void conv_silu_kernel(
    const float* __restrict__ cw, const float* __restrict__ cb)
{
    const int bid = blockIdx.x;          // 0..127
    const int T = bid >> 6;
    const int h0 = (bid & 63) * 4;
    __shared__ float rows[2][6][520];
    __shared__ float wsh[36];
    __shared__ float bsh[2];
    const int t = threadIdx.x;
    if (t < 36) wsh[t] = cw[t];
    if (t < 2) bsh[t] = cb[t];
    const __nv_bfloat16* Pb = g_Pbf + (size_t)T * HROWS * D2;

    for (int idx = t; idx < 2 * 6 * 64; idx += 256) {
        int i = idx / 384;
        int rem = idx - i * 384;
        int r = rem >> 6;
        int c8 = rem & 63;
        int hh = h0 + r - 1;
        float4 f0 = make_float4(0.f, 0.f, 0.f, 0.f), f1 = f0;
        if (hh >= 0 && hh < Lh) {
            uint4 q = *(const uint4*)(Pb + (size_t)(i * Lh + hh) * D2 + c8 * 8);
            const __nv_bfloat162* h = (const __nv_bfloat162*)&q;
            float2 a0 = __bfloat1622float2(h[0]), a1 = __bfloat1622float2(h[1]);
            float2 a2 = __bfloat1622float2(h[2]), a3 = __bfloat1622float2(h[3]);
            f0 = make_float4(a0.x, a0.y, a1.x, a1.y);
            f1 = make_float4(a2.x, a2.y, a3.x, a3.y);
        }
        *(float4*)&rows[i][r][c8 * 8] = f0;
        *(float4*)&rows[i][r][c8 * 8 + 4] = f1;
    }
    __syncthreads();

    #pragma unroll
    for (int oh = 0; oh < 4; oh++) {
        #pragma unroll
        for (int ws = 0; ws < 2; ws++) {
            int w = t + ws * 256;
            float acc0 = bsh[0], acc1 = bsh[1];
            #pragma unroll
            for (int i = 0; i < 2; i++)
                #pragma unroll
                for (int kh = 0; kh < 3; kh++) {
                    float dl = (w == 0)      ? 0.f : rows[i][oh + kh][w - 1];
                    float dc = rows[i][oh + kh][w];
                    float dr = (w == D2 - 1) ? 0.f : rows[i][oh + kh][w + 1];
                    acc0 += dl * wsh[i * 9 + kh * 3 + 0]
                          + dc * wsh[i * 9 + kh * 3 + 1]
                          + dr * wsh[i * 9 + kh * 3 + 2];
                    acc1 += dl * wsh[18 + i * 9 + kh * 3 + 0]
                          + dc * wsh[18 + i * 9 + kh * 3 + 1]
                          + dr * wsh[18 + i * 9 + kh * 3 + 2];
                }
            int h = h0 + oh;
            g_XCbf[((size_t)T * HROWS + 0 * Lh + h) * D2 + w] = __float2bfloat16(silu_f(acc0));
            g_XCbf[((size_t)T * HROWS + 1 * Lh + h) * D2 + w] = __float2bfloat16(silu_f(acc1));
        }
    }
}

// ---------------- mega2: delta GEMM (0..255) + Bm GEMM (256..319) ------------
__global__ __launch_bounds__(128) void mega2_kernel(
    const float* __restrict__ fc1_b, const float* __restrict__ fc2_b)
{
    __shared__ uint32_t sm[2 * GST64];
    const int bid = blockIdx.x;
    if (bid < 256) {
        int row0 = (bid >> 3) * 32, col0 = (bid & 7) * 64;
        gemm64_tile<2, 0>(sm, g_XCbf + (size_t)row0 * D2, g_W1bf,
                          fc1_b, g_DELTA, D2, D2, row0, col0);
    } else {
        int b2 = bid - 256;               // 0..63
        int row0 = (b2 >> 1) * 32, col0 = (b2 & 1) * 64;
        gemm64_tile<0, 1>(sm, g_XCbf + (size_t)row0 * D2, g_W2bf,
                          fc2_b, g_BMbf, Sn, D2, row0, col0);
    }
}

// ---------------- SSM: 4-slab BK=64 GEMM + S2 + Horner + silu ----------------
__global__ __launch_bounds__(128) void ssm_kernel()
{
    extern __shared__ uint32_t dsm[];
    __shared__ float s2s[32];
    const int t = threadIdx.x;
    const int lane = t & 31, wn = t >> 5;
    const int g = lane >> 2, tig = lane & 3;
    const int row0 = blockIdx.y * 32, col0 = blockIdx.x * 64;
    const uint32_t sbase = (uint32_t)__cvta_generic_to_shared(dsm);

    // cp.async mapping
    const __nv_bfloat16* Agp[2]; uint32_t Aso[2];
    #pragma unroll
    for (int i = 0; i < 2; i++) {
        int c = t + i * 128, row = c >> 3, cw = c & 7;
        Agp[i] = g_BMbf + (size_t)(row0 + row) * Sn + cw * 8;
        Aso[i] = (uint32_t)(row * SR64 + cw * 4) * 4u;
    }
    const __nv_bfloat16* Egp[4]; uint32_t Eso[4];
    #pragma unroll
    for (int i = 0; i < 4; i++) {
        int c = t + i * 128, row = c >> 3, cw = c & 7;
        Egp[i] = g_Ebf + (size_t)(col0 + row) * Sn + cw * 8;  // + j*D2*Sn per slab
        Eso[i] = (uint32_t)(row * SR64 + cw * 4) * 4u;        // + (AW64 + j*BW64)
    }

    // prologue stage 0
    #pragma unroll
    for (int i = 0; i < 2; i++) cpa16(sbase + Aso[i], Agp[i]);
    #pragma unroll
    for (int j = 0; j < 4; j++)
        #pragma unroll
        for (int i = 0; i < 4; i++)
            cpa16(sbase + (uint32_t)(AW64 + j * BW64) * 4u + Eso[i],
                  Egp[i] + (size_t)j * D2 * Sn);
    CP_COMMIT();

    // per-row sum of Bm^2 (deterministic shuffle reduce)
    float s2p = 0.f;
    {
        const uint4* bm = (const uint4*)(g_BMbf + (size_t)(row0 + (t >> 2)) * Sn
                                         + (t & 3) * 32);
        #pragma unroll
        for (int i = 0; i < 4; i++) {
            uint4 q = bm[i];
            const __nv_bfloat162* h = (const __nv_bfloat162*)&q;
            #pragma unroll
            for (int p = 0; p < 4; p++) {
                float2 f = __bfloat1622float2(h[p]);
                s2p += f.x * f.x + f.y * f.y;
            }
        }
    }
    s2p += __shfl_xor_sync(0xffffffffu, s2p, 1);
    s2p += __shfl_xor_sync(0xffffffffu, s2p, 2);
    if ((t & 3) == 0) s2s[t >> 2] = s2p;

    const int mM = lane >> 3;
    const int rA = ((mM & 1) << 3) + (lane & 7);
    const uint32_t cbB = (uint32_t)((mM >> 1) * 16);

    float c[4][2][2][4] = {};

    for (int kt = 0; kt < 2; kt++) {   // K = Sn = 128, BK = 64
        if (kt + 1 < 2) {
            uint32_t nb = sbase + (uint32_t)(((kt + 1) & 1) * SST64) * 4u;
            int ko = (kt + 1) * 64;
            #pragma unroll
            for (int i = 0; i < 2; i++) cpa16(nb + Aso[i], Agp[i] + ko);
            #pragma unroll
            for (int j = 0; j < 4; j++)
                #pragma unroll
                for (int i = 0; i < 4; i++)
                    cpa16(nb + (uint32_t)(AW64 + j * BW64) * 4u + Eso[i],
                          Egp[i] + (size_t)j * D2 * Sn + ko);
        }
        CP_COMMIT();
        CP_WAIT1();
        __syncthreads();
        uint32_t sa = sbase + (uint32_t)((kt & 1) * SST64) * 4u;
        #pragma unroll
        for (int k16 = 0; k16 < 4; k16++) {
            uint32_t off = (uint32_t)(k16 * 32) + cbB;
            uint32_t afr[2][4];
            ldsm_x4(afr[0][0], afr[0][1], afr[0][2], afr[0][3],
                    sa + (uint32_t)(rA * SR64) * 4u + off);
            ldsm_x4(afr[1][0], afr[1][1], afr[1][2], afr[1][3],
                    sa + (uint32_t)((16 + rA) * SR64) * 4u + off);
            #pragma unroll
            for (int j = 0; j < 4; j++) {
                uint32_t b0, b1, b2, b3;
                ldsm_x4(b0, b1, b2, b3,
                        sa + (uint32_t)(AW64 + j * BW64) * 4u
                           + (uint32_t)((wn * 16 + rA) * SR64) * 4u + off);
                #pragma unroll
                for (int mi = 0; mi < 2; mi++) {
                    mma_bf16(c[j][mi][0], afr[mi][0], afr[mi][1], afr[mi][2], afr[mi][3], b0, b2);
                    mma_bf16(c[j][mi][1], afr[mi][0], afr[mi][1], afr[mi][2], afr[mi][3], b1, b3);
                }
            }
        }
        __syncthreads();
    }

    // epilogue: Horner in u + x*delta*S2, then silu
    #pragma unroll
    for (int mi = 0; mi < 2; mi++) {
        #pragma unroll
        for (int half = 0; half < 2; half++) {
            int rl = mi * 16 + g + half * 8;
            int r = row0 + rl;
            float s2 = s2s[rl];
            #pragma unroll
            for (int ni = 0; ni < 2; ni++) {
                int d = col0 + wn * 16 + ni * 8 + 2 * tig;
                float2 dl = *(const float2*)&g_DELTA[(size_t)r * D2 + d];
                float2 xc = __bfloat1622float2(
                    *(const __nv_bfloat162*)(g_XCbf + (size_t)r * D2 + d));
                int q0 = half * 2;
                float u0 = dl.x - LN2F, u1 = dl.y - LN2F;
                float s0 = c[0][mi][ni][q0]
                         + u0 * (c[1][mi][ni][q0] + u0 * (c[2][mi][ni][q0] + u0 * c[3][mi][ni][q0]));
                float s1 = c[0][mi][ni][q0 + 1]
                         + u1 * (c[1][mi][ni][q0 + 1] + u1 * (c[2][mi][ni][q0 + 1] + u1 * c[3][mi][ni][q0 + 1]));
                s0 += xc.x * dl.x * s2;
                s1 += xc.y * dl.y * s2;
                *(float2*)&g_XS[(size_t)r * D2 + d] = make_float2(silu_f(s0), silu_f(s1));
            }
        }
    }
}

// ---------------- out GEMM with fused comb (register-staged, BK=32) ----------
__global__ __launch_bounds__(128) void out_kernel(
    const float* __restrict__ out_W, const float* __restrict__ out_b,
    float* __restrict__ out)
{
    __shared__ uint32_t smbuf[OA32W + OB64W];
    uint32_t* As = smbuf;
    uint32_t* Bs = smbuf + OA32W;
    const int t = threadIdx.x;
    const int lane = t & 31, wn = t >> 5;
    const int g = lane >> 2, tig = lane & 3;
    const int row0 = blockIdx.y * 32, col0 = blockIdx.x * 64;
    const int ar = t >> 2, ac = (t & 3) * 8;
    const int N = Dm, K = D2;

    const float* Ap  = g_XS + (size_t)(row0 + ar) * K + ac;
    const float* A2p = g_XS + (size_t)(HROWS + row0 + ar) * K + ac;
    const float* A3p = g_RES + (size_t)(row0 + ar) * K + ac;
    const float* Wp0 = out_W + (size_t)(col0 + ar) * K + ac;
    const float* Wp1 = out_W + (size_t)(col0 + ar + 32) * K + ac;

    float c[2][2][4] = {};
    const int ntiles = K >> 5;
    uint4 ab, wb0, wb1;

#define LOAD_AB(ko) do { \
    float4 u = *(const float4*)(Ap + (ko)); \
    float4 v = *(const float4*)(Ap + (ko) + 4); \
    float4 u2 = *(const float4*)(A2p + (ko)), u3 = *(const float4*)(A3p + (ko)); \
    float4 v2 = *(const float4*)(A2p + (ko) + 4), v3 = *(const float4*)(A3p + (ko) + 4); \
    u.x = (u.x + u2.x) * u3.x; u.y = (u.y + u2.y) * u3.y; \
    u.z = (u.z + u2.z) * u3.z; u.w = (u.w + u2.w) * u3.w; \
    v.x = (v.x + v2.x) * v3.x; v.y = (v.y + v2.y) * v3.y; \
    v.z = (v.z + v2.z) * v3.z; v.w = (v.w + v2.w) * v3.w; \
    ab = pack8(u, v); \
    { float4 xx = *(const float4*)(Wp0 + (ko)); \
      float4 yy = *(const float4*)(Wp0 + (ko) + 4); \
      wb0 = pack8(xx, yy); } \
    { float4 xx = *(const float4*)(Wp1 + (ko)); \
      float4 yy = *(const float4*)(Wp1 + (ko) + 4); \
      wb1 = pack8(xx, yy); } \
} while (0)

    LOAD_AB(0);
    for (int kt = 0; kt < ntiles; kt++) {
        __syncthreads();
        *(uint4*)&As[ar * OSROW + (t & 3) * 4] = ab;
        *(uint4*)&Bs[ar * OSROW + (t & 3) * 4] = wb0;
        *(uint4*)&Bs[(ar + 32) * OSROW + (t & 3) * 4] = wb1;
        __syncthreads();
        if (kt + 1 < ntiles) LOAD_AB((kt + 1) * 32);
        #pragma unroll
        for (int k16 = 0; k16 < 2; k16++) {
            const int kb = k16 * 8;
            uint32_t afr[2][4], bfr[2][2];
            #pragma unroll
            for (int mi = 0; mi < 2; mi++) {
                int r = mi * 16 + g;
                afr[mi][0] = As[r * OSROW + kb + tig];
                afr[mi][1] = As[(r + 8) * OSROW + kb + tig];
                afr[mi][2] = As[r * OSROW + kb + tig + 4];
                afr[mi][3] = As[(r + 8) * OSROW + kb + tig + 4];
            }
            #pragma unroll
            for (int ni = 0; ni < 2; ni++) {
                int n = wn * 16 + ni * 8 + g;
                bfr[ni][0] = Bs[n * OSROW + kb + tig];
                bfr[ni][1] = Bs[n * OSROW + kb + tig + 4];
            }
            #pragma unroll
            for (int mi = 0; mi < 2; mi++)
                #pragma unroll
                for (int ni = 0; ni < 2; ni++)
                    mma_bf16(c[mi][ni], afr[mi][0], afr[mi][1], afr[mi][2],
                             afr[mi][3], bfr[ni][0], bfr[ni][1]);
        }
    }
#undef LOAD_AB

    #pragma unroll
    for (int mi = 0; mi < 2; mi++) {
        int r = row0 + mi * 16 + g;
        #pragma unroll
        for (int ni = 0; ni < 2; ni++) {
            int n = col0 + wn * 16 + ni * 8 + 2 * tig;
            float b0 = out_b[n], b1 = out_b[n + 1];
            *(float2*)&out[(size_t)r * N + n] =
                make_float2(c[mi][ni][0] + b0, c[mi][ni][1] + b1);
            *(float2*)&out[(size_t)(r + 8) * N + n] =
                make_float2(c[mi][ni][2] + b0, c[mi][ni][3] + b1);
        }
    }
}

// ---------------- launch ----------------
extern "C" void kernel_launch(void* const* d_in, const int* in_sizes, int n_in,
                              void* d_out, int out_size)
{
    const float* x      = (const float*)d_in[0];
    const float* mouth  = (const float*)d_in[1];
    const float* norm_w = (const float*)d_in[2];
    const float* inp_W  = (const float*)d_in[3];
    const float* inp_b  = (const float*)d_in[4];
    const float* out_W  = (const float*)d_in[5];
    const float* out_b  = (const float*)d_in[6];
    const float* Dlin_W = (const float*)d_in[7];
    const float* Dlin_b = (const float*)d_in[8];
    const float* conv_W = (const float*)d_in[9];
    const float* conv_b = (const float*)d_in[10];
    const float* fc1_W  = (const float*)d_in[11];
    const float* fc1_b  = (const float*)d_in[12];
    const float* fc2_W  = (const float*)d_in[13];
    const float* fc2_b  = (const float*)d_in[14];
    const float* A      = (const float*)d_in[15];

    const int SSM_SMEM = 2 * SST64 * 4;   // 82944 B
    cudaFuncSetAttribute(ssm_kernel,
                         cudaFuncAttributeMaxDynamicSharedMemorySize, SSM_SMEM);

    // 1) XNbf + E bf16 + weight bf16
    prep_kernel<<<672, 256>>>(x, mouth, norm_w, A, inp_W, Dlin_W, fc1_W, fc2_W);
    // 2) inp GEMM -> Pbf, res GEMM -> RES
    mega1_kernel<<<384, 128>>>(inp_b, Dlin_b);
    // 3) conv + silu -> XCbf
    conv_silu_kernel<<<128, 256>>>(conv_W, conv_b);
    // 4) delta GEMM -> DELTA, Bm GEMM -> BMbf
    mega2_kernel<<<320, 128>>>(fc1_b, fc2_b);
    // 5) ssm (4-slab GEMM + S2 + Horner + silu) -> XS
    ssm_kernel<<<dim3(D2 / 64, NROWS / 32), 128, SSM_SMEM>>>();
    // 6) out = ((XS_x + XS_m) * RES) @ out_W^T + out_b
    out_kernel<<<dim3(Dm / 64, HROWS / 32), 128>>>(out_W, out_b, (float*)d_out);
}

// round 16
// speedup vs baseline: 1.8478x; 1.0397x over previous
#include <cuda_runtime.h>
#include <cuda_bf16.h>
#include <math.h>
#include <stdint.h>

// Problem constants
#define Dm     256
#define D2     512
#define Sn     128
#define Lh     256
#define NROWS  1024
#define HROWS  512
#define LN2F   0.69314718055994531f

// BK=64 tile geometry (words = uint32)
#define SR64   36                  // row stride: 32 data words (64 bf16) + 4 pad
#define AW64   (32 * SR64)         // 32x64 bf16 A tile
#define BW64   (64 * SR64)         // 64x64 bf16 B tile
#define GST64  (AW64 + BW64)       // gemm stage words
#define SST64  (AW64 + 4 * BW64)   // ssm stage words

// BK=32 constants (out kernel only)
#define OSROW  20
#define OA32W  (32 * OSROW)
#define OB64W  (64 * OSROW)

// ---------------- scratch ----------------
__device__ __nv_bfloat16 g_XNbf[NROWS * Dm];
__device__ __nv_bfloat16 g_Wibf[D2 * Dm];
__device__ __nv_bfloat16 g_Wdbf[D2 * Dm];
__device__ __nv_bfloat16 g_W1bf[D2 * D2];
__device__ __nv_bfloat16 g_W2bf[Sn * D2];
__device__ __nv_bfloat16 g_Pbf[NROWS * D2];
__device__ __nv_bfloat16 g_XCbf[NROWS * D2];
__device__ float         g_DELTA[NROWS * D2];
__device__ __nv_bfloat16 g_BMbf[NROWS * Sn];
__device__ __nv_bfloat16 g_Ebf[4 * D2 * Sn];
__device__ float         g_XS[NROWS * D2];
__device__ float         g_RES[HROWS * D2];

__device__ __forceinline__ float silu_f(float v) { return v / (1.f + expf(-v)); }
__device__ __forceinline__ float softplus_f(float v) {
    return fmaxf(v, 0.f) + log1pf(expf(-fabsf(v)));
}
__device__ __forceinline__ uint32_t pk(float a, float b) {
    __nv_bfloat162 h = __floats2bfloat162_rn(a, b);
    return *reinterpret_cast<uint32_t*>(&h);
}
__device__ __forceinline__ uint4 pack8(float4 u, float4 v) {
    return make_uint4(pk(u.x, u.y), pk(u.z, u.w), pk(v.x, v.y), pk(v.z, v.w));
}
__device__ __forceinline__ void mma_bf16(float c[4],
    uint32_t a0, uint32_t a1, uint32_t a2, uint32_t a3,
    uint32_t b0, uint32_t b1)
{
    asm("mma.sync.aligned.m16n8k16.row.col.f32.bf16.bf16.f32 "
        "{%0,%1,%2,%3}, {%4,%5,%6,%7}, {%8,%9}, {%0,%1,%2,%3};"
        : "+f"(c[0]), "+f"(c[1]), "+f"(c[2]), "+f"(c[3])
        : "r"(a0), "r"(a1), "r"(a2), "r"(a3), "r"(b0), "r"(b1));
}
__device__ __forceinline__ void ldsm_x4(uint32_t& r0, uint32_t& r1,
                                        uint32_t& r2, uint32_t& r3, uint32_t addr)
{
    asm volatile("ldmatrix.sync.aligned.m8n8.x4.shared.b16 {%0,%1,%2,%3}, [%4];"
                 : "=r"(r0), "=r"(r1), "=r"(r2), "=r"(r3) : "r"(addr));
}
__device__ __forceinline__ void cpa16(uint32_t saddr, const void* g) {
    asm volatile("cp.async.ca.shared.global [%0], [%1], 16;"
                 :: "r"(saddr), "l"(g) : "memory");
}
#define CP_COMMIT() asm volatile("cp.async.commit_group;" ::: "memory")
#define CP_WAIT1()  asm volatile("cp.async.wait_group 1;" ::: "memory")
#define CP_WAIT0()  asm volatile("cp.async.wait_group 0;" ::: "memory")

// ---------------- prep: XNbf + E slabs + weight->bf16 ------------------------
__global__ __launch_bounds__(256) void prep_kernel(
    const float* __restrict__ x, const float* __restrict__ mouth,
    const float* __restrict__ norm_w, const float* __restrict__ A,
    const float* __restrict__ inp_W, const float* __restrict__ Dlin_W,
    const float* __restrict__ fc1_W, const float* __restrict__ fc2_W)
{
    const int bid = blockIdx.x, t = threadIdx.x;
    if (bid < 128) {
        int warp = t >> 5, lane = t & 31;
        int r = bid * 8 + warp;
        const float* src = (r < HROWS) ? (x + (size_t)r * Dm)
                                       : (mouth + (size_t)(r - HROWS) * Dm);
        float4 v0 = ((const float4*)src)[lane * 2];
        float4 v1 = ((const float4*)src)[lane * 2 + 1];
        float s = v0.x * v0.x + v0.y * v0.y + v0.z * v0.z + v0.w * v0.w
                + v1.x * v1.x + v1.y * v1.y + v1.z * v1.z + v1.w * v1.w;
        #pragma unroll
        for (int o = 16; o; o >>= 1) s += __shfl_xor_sync(0xffffffffu, s, o);
        float rinv = 1.f / sqrtf(s + 1e-5f);
        float4 w0 = ((const float4*)norm_w)[lane * 2];
        float4 w1 = ((const float4*)norm_w)[lane * 2 + 1];
        v0.x *= rinv * w0.x; v0.y *= rinv * w0.y; v0.z *= rinv * w0.z; v0.w *= rinv * w0.w;
        v1.x *= rinv * w1.x; v1.y *= rinv * w1.y; v1.z *= rinv * w1.z; v1.w *= rinv * w1.w;
        *(uint4*)(g_XNbf + (size_t)r * Dm + lane * 8) = pack8(v0, v1);
    } else if (bid < 384) {
        int idx = (bid - 128) * 256 + t;   // d*128 + n
        float a = A[idx];
        float e0 = exp2f(a);               // exp(ln2 * a)
        g_Ebf[0 * D2 * Sn + idx] = __float2bfloat16(e0);
        g_Ebf[1 * D2 * Sn + idx] = __float2bfloat16(a * e0);
        g_Ebf[2 * D2 * Sn + idx] = __float2bfloat16(0.5f * a * a * e0);
        g_Ebf[3 * D2 * Sn + idx] = __float2bfloat16((1.f / 6.f) * a * a * a * e0);
    } else {
        int wb = bid - 384;                // 0..287
        const float* src; __nv_bfloat16* dst; int base;
        if (wb < 64)       { src = inp_W;  dst = g_Wibf; base = wb * 2048; }
        else if (wb < 128) { src = Dlin_W; dst = g_Wdbf; base = (wb - 64) * 2048; }
        else if (wb < 256) { src = fc1_W;  dst = g_W1bf; base = (wb - 128) * 2048; }
        else               { src = fc2_W;  dst = g_W2bf; base = (wb - 256) * 2048; }
        int idx = base + t * 8;
        float4 u = ((const float4*)(src + idx))[0];
        float4 v = ((const float4*)(src + idx))[1];
        *(uint4*)(dst + idx) = pack8(u, v);
    }
}

// ---------------- BK=64 bf16 GEMM core: 32x64 tile, 4 warps, ldmatrix --------
// 3-stage cp.async pipeline, one __syncthreads per K-iteration.
template<int ACT, int CBF16, int K>
__device__ __forceinline__ void gemm64_tile(
    uint32_t* sm,   // 3 * GST64 words
    const __nv_bfloat16* __restrict__ A_t, const __nv_bfloat16* __restrict__ W,
    const float* __restrict__ bias, void* Cv,
    int N, int row0, int col0)
{
    const int t = threadIdx.x;
    const int lane = t & 31, wn = t >> 5;
    const int g = lane >> 2, tig = lane & 3;
    constexpr int ntk = K >> 6;
    const uint32_t sbase = (uint32_t)__cvta_generic_to_shared(sm);

    const __nv_bfloat16* Agp[2]; uint32_t Aso[2];
    #pragma unroll
    for (int i = 0; i < 2; i++) {
        int c = t + i * 128, row = c >> 3, cw = c & 7;
        Agp[i] = A_t + (size_t)row * K + cw * 8;
        Aso[i] = (uint32_t)(row * SR64 + cw * 4) * 4u;
    }
    const __nv_bfloat16* Wgp[4]; uint32_t Wso[4];
    #pragma unroll
    for (int i = 0; i < 4; i++) {
        int c = t + i * 128, row = c >> 3, cw = c & 7;
        Wgp[i] = W + (size_t)(col0 + row) * K + cw * 8;
        Wso[i] = (uint32_t)(AW64 + row * SR64 + cw * 4) * 4u;
    }

    // prologue: stages 0 and 1
    #pragma unroll
    for (int i = 0; i < 2; i++) cpa16(sbase + Aso[i], Agp[i]);
    #pragma unroll
    for (int i = 0; i < 4; i++) cpa16(sbase + Wso[i], Wgp[i]);
    CP_COMMIT();
    if (ntk > 1) {
        uint32_t nb = sbase + (uint32_t)GST64 * 4u;
        #pragma unroll
        for (int i = 0; i < 2; i++) cpa16(nb + Aso[i], Agp[i] + 64);
        #pragma unroll
        for (int i = 0; i < 4; i++) cpa16(nb + Wso[i], Wgp[i] + 64);
    }
    CP_COMMIT();

    const int mM = lane >> 3;
    const int rA = ((mM & 1) << 3) + (lane & 7);
    const uint32_t cbB = (uint32_t)((mM >> 1) * 16);

    float c[2][2][4] = {};

    #pragma unroll
    for (int kt = 0; kt < ntk; kt++) {
        CP_WAIT1();            // stage kt complete
        __syncthreads();       // publish stage kt; retire reads of buf (kt-1)%3
        if (kt + 2 < ntk) {
            uint32_t nb = sbase + (uint32_t)(((kt + 2) % 3) * GST64) * 4u;
            int ko = (kt + 2) * 64;
            #pragma unroll
            for (int i = 0; i < 2; i++) cpa16(nb + Aso[i], Agp[i] + ko);
            #pragma unroll
            for (int i = 0; i < 4; i++) cpa16(nb + Wso[i], Wgp[i] + ko);
        }
        CP_COMMIT();
        uint32_t sa = sbase + (uint32_t)((kt % 3) * GST64) * 4u;
        uint32_t sb = sa + (uint32_t)AW64 * 4u;
        #pragma unroll
        for (int k16 = 0; k16 < 4; k16++) {
            uint32_t off = (uint32_t)(k16 * 32) + cbB;
            uint32_t afr[2][4], b0, b1, b2, b3;
            ldsm_x4(afr[0][0], afr[0][1], afr[0][2], afr[0][3],
                    sa + (uint32_t)(rA * SR64) * 4u + off);
            ldsm_x4(afr[1][0], afr[1][1], afr[1][2], afr[1][3],
                    sa + (uint32_t)((16 + rA) * SR64) * 4u + off);
            ldsm_x4(b0, b1, b2, b3,
                    sb + (uint32_t)((wn * 16 + rA) * SR64) * 4u + off);
            #pragma unroll
            for (int mi = 0; mi < 2; mi++) {
                mma_bf16(c[mi][0], afr[mi][0], afr[mi][1], afr[mi][2], afr[mi][3], b0, b2);
                mma_bf16(c[mi][1], afr[mi][0], afr[mi][1], afr[mi][2], afr[mi][3], b1, b3);
            }
        }
    }

    #pragma unroll
    for (int mi = 0; mi < 2; mi++) {
        int r = row0 + mi * 16 + g;
        #pragma unroll
        for (int ni = 0; ni < 2; ni++) {
            int n = col0 + wn * 16 + ni * 8 + 2 * tig;
            float b0 = bias[n], b1 = bias[n + 1];
            float v0 = c[mi][ni][0] + b0, v1 = c[mi][ni][1] + b1;
            float v2 = c[mi][ni][2] + b0, v3 = c[mi][ni][3] + b1;
            if (ACT == 1) { v0 = silu_f(v0); v1 = silu_f(v1); v2 = silu_f(v2); v3 = silu_f(v3); }
            else if (ACT == 2) { v0 = softplus_f(v0); v1 = softplus_f(v1); v2 = softplus_f(v2); v3 = softplus_f(v3); }
            if (CBF16) {
                __nv_bfloat16* Cb = (__nv_bfloat16*)Cv;
                *(uint32_t*)(Cb + (size_t)r * N + n) = pk(v0, v1);
                *(uint32_t*)(Cb + (size_t)(r + 8) * N + n) = pk(v2, v3);
            } else {
                float* Cf = (float*)Cv;
                *(float2*)&Cf[(size_t)r * N + n] = make_float2(v0, v1);
                *(float2*)&Cf[(size_t)(r + 8) * N + n] = make_float2(v2, v3);
            }
        }
    }
}

// ---------------- mega1: inp GEMM (0..255) + res GEMM (256..383) -------------
__global__ __launch_bounds__(128) void mega1_kernel(
    const float* __restrict__ inp_b, const float* __restrict__ Dlin_b)
{
    __shared__ uint32_t sm[3 * GST64];
    const int bid = blockIdx.x;
    if (bid < 256) {
        int row0 = (bid >> 3) * 32, col0 = (bid & 7) * 64;
        gemm64_tile<0, 1, Dm>(sm, g_XNbf + (size_t)row0 * Dm, g_Wibf,
                              inp_b, g_Pbf, D2, row0, col0);
    } else {
        int b2 = bid - 256;
        int row0 = (b2 >> 3) * 32, col0 = (b2 & 7) * 64;
        gemm64_tile<1, 0, Dm>(sm, g_XNbf + (size_t)row0 * Dm, g_Wdbf,
                              Dlin_b, g_RES, D2, row0, col0);
    }
}

// ---------------- conv 3x3 SAME + silu, h-tile = 4, bf16 in/out --------------
__global__ __launch_bounds__(256) void conv_silu_kernel(
    const float* __restrict__ cw, const float* __restrict__ cb)
{
    const int bid = blockIdx.x;          // 0..127
    const int T = bid >> 6;
    const int h0 = (bid & 63) * 4;
    __shared__ float rows[2][6][520];
    __shared__ float wsh[36];
    __shared__ float bsh[2];
    const int t = threadIdx.x;
    if (t < 36) wsh[t] = cw[t];
    if (t < 2) bsh[t] = cb[t];
    const __nv_bfloat16* Pb = g_Pbf + (size_t)T * HROWS * D2;

    for (int idx = t; idx < 2 * 6 * 64; idx += 256) {
        int i = idx / 384;
        int rem = idx - i * 384;
        int r = rem >> 6;
        int c8 = rem & 63;
        int hh = h0 + r - 1;
        float4 f0 = make_float4(0.f, 0.f, 0.f, 0.f), f1 = f0;
        if (hh >= 0 && hh < Lh) {
            uint4 q = *(const uint4*)(Pb + (size_t)(i * Lh + hh) * D2 + c8 * 8);
            const __nv_bfloat162* h = (const __nv_bfloat162*)&q;
            float2 a0 = __bfloat1622float2(h[0]), a1 = __bfloat1622float2(h[1]);
            float2 a2 = __bfloat1622float2(h[2]), a3 = __bfloat1622float2(h[3]);
            f0 = make_float4(a0.x, a0.y, a1.x, a1.y);
            f1 = make_float4(a2.x, a2.y, a3.x, a3.y);
        }
        *(float4*)&rows[i][r][c8 * 8] = f0;
        *(float4*)&rows[i][r][c8 * 8 + 4] = f1;
    }
    __syncthreads();

    #pragma unroll
    for (int oh = 0; oh < 4; oh++) {
        #pragma unroll
        for (int ws = 0; ws < 2; ws++) {
            int w = t + ws * 256;
            float acc0 = bsh[0], acc1 = bsh[1];
            #pragma unroll
            for (int i = 0; i < 2; i++)
                #pragma unroll
                for (int kh = 0; kh < 3; kh++) {
                    float dl = (w == 0)      ? 0.f : rows[i][oh + kh][w - 1];
                    float dc = rows[i][oh + kh][w];
                    float dr = (w == D2 - 1) ? 0.f : rows[i][oh + kh][w + 1];
                    acc0 += dl * wsh[i * 9 + kh * 3 + 0]
                          + dc * wsh[i * 9 + kh * 3 + 1]
                          + dr * wsh[i * 9 + kh * 3 + 2];
                    acc1 += dl * wsh[18 + i * 9 + kh * 3 + 0]
                          + dc * wsh[18 + i * 9 + kh * 3 + 1]
                          + dr * wsh[18 + i * 9 + kh * 3 + 2];
                }
            int h = h0 + oh;
            g_XCbf[((size_t)T * HROWS + 0 * Lh + h) * D2 + w] = __float2bfloat16(silu_f(acc0));
            g_XCbf[((size_t)T * HROWS + 1 * Lh + h) * D2 + w] = __float2bfloat16(silu_f(acc1));
        }
    }
}

// ---------------- mega2: delta GEMM (0..255) + Bm GEMM (256..319) ------------
__global__ __launch_bounds__(128) void mega2_kernel(
    const float* __restrict__ fc1_b, const float* __restrict__ fc2_b)
{
    __shared__ uint32_t sm[3 * GST64];
    const int bid = blockIdx.x;
    if (bid < 256) {
        int row0 = (bid >> 3) * 32, col0 = (bid & 7) * 64;
        gemm64_tile<2, 0, D2>(sm, g_XCbf + (size_t)row0 * D2, g_W1bf,
                              fc1_b, g_DELTA, D2, row0, col0);
    } else {
        int b2 = bid - 256;               // 0..63
        int row0 = (b2 >> 1) * 32, col0 = (b2 & 1) * 64;
        gemm64_tile<0, 1, D2>(sm, g_XCbf + (size_t)row0 * D2, g_W2bf,
                              fc2_b, g_BMbf, Sn, row0, col0);
    }
}

// ---------------- SSM: 4-slab BK=64 GEMM + S2 + Horner + silu ----------------
// K=128 -> 2 stages, both preloaded; one sync per iteration.
__global__ __launch_bounds__(128) void ssm_kernel()
{
    extern __shared__ uint32_t dsm[];
    __shared__ float s2s[32];
    const int t = threadIdx.x;
    const int lane = t & 31, wn = t >> 5;
    const int g = lane >> 2, tig = lane & 3;
    const int row0 = blockIdx.y * 32, col0 = blockIdx.x * 64;
    const uint32_t sbase = (uint32_t)__cvta_generic_to_shared(dsm);

    const __nv_bfloat16* Agp[2]; uint32_t Aso[2];
    #pragma unroll
    for (int i = 0; i < 2; i++) {
        int c = t + i * 128, row = c >> 3, cw = c & 7;
        Agp[i] = g_BMbf + (size_t)(row0 + row) * Sn + cw * 8;
        Aso[i] = (uint32_t)(row * SR64 + cw * 4) * 4u;
    }
    const __nv_bfloat16* Egp[4]; uint32_t Eso[4];
    #pragma unroll
    for (int i = 0; i < 4; i++) {
        int c = t + i * 128, row = c >> 3, cw = c & 7;
        Egp[i] = g_Ebf + (size_t)(col0 + row) * Sn + cw * 8;
        Eso[i] = (uint32_t)(row * SR64 + cw * 4) * 4u;
    }

    // prologue: both stages
    #pragma unroll
    for (int kt = 0; kt < 2; kt++) {
        uint32_t sb = sbase + (uint32_t)(kt * SST64) * 4u;
        int ko = kt * 64;
        #pragma unroll
        for (int i = 0; i < 2; i++) cpa16(sb + Aso[i], Agp[i] + ko);
        #pragma unroll
        for (int j = 0; j < 4; j++)
            #pragma unroll
            for (int i = 0; i < 4; i++)
                cpa16(sb + (uint32_t)(AW64 + j * BW64) * 4u + Eso[i],
                      Egp[i] + (size_t)j * D2 * Sn + ko);
        CP_COMMIT();
    }

    // per-row sum of Bm^2 (deterministic shuffle reduce)
    float s2p = 0.f;
    {
        const uint4* bm = (const uint4*)(g_BMbf + (size_t)(row0 + (t >> 2)) * Sn
                                         + (t & 3) * 32);
        #pragma unroll
        for (int i = 0; i < 4; i++) {
            uint4 q = bm[i];
            const __nv_bfloat162* h = (const __nv_bfloat162*)&q;
            #pragma unroll
            for (int p = 0; p < 4; p++) {
                float2 f = __bfloat1622float2(h[p]);
                s2p += f.x * f.x + f.y * f.y;
            }
        }
    }
    s2p += __shfl_xor_sync(0xffffffffu, s2p, 1);
    s2p += __shfl_xor_sync(0xffffffffu, s2p, 2);
    if ((t & 3) == 0) s2s[t >> 2] = s2p;

    const int mM = lane >> 3;
    const int rA = ((mM & 1) << 3) + (lane & 7);
    const uint32_t cbB = (uint32_t)((mM >> 1) * 16);

    float c[4][2][2][4] = {};

    #pragma unroll
    for (int kt = 0; kt < 2; kt++) {
        if (kt == 0) CP_WAIT1(); else CP_WAIT0();
        __syncthreads();
        uint32_t sa = sbase + (uint32_t)(kt * SST64) * 4u;
        #pragma unroll
        for (int k16 = 0; k16 < 4; k16++) {
            uint32_t off = (uint32_t)(k16 * 32) + cbB;
            uint32_t afr[2][4];
            ldsm_x4(afr[0][0], afr[0][1], afr[0][2], afr[0][3],
                    sa + (uint32_t)(rA * SR64) * 4u + off);
            ldsm_x4(afr[1][0], afr[1][1], afr[1][2], afr[1][3],
                    sa + (uint32_t)((16 + rA) * SR64) * 4u + off);
            #pragma unroll
            for (int j = 0; j < 4; j++) {
                uint32_t b0, b1, b2, b3;
                ldsm_x4(b0, b1, b2, b3,
                        sa + (uint32_t)(AW64 + j * BW64) * 4u
                           + (uint32_t)((wn * 16 + rA) * SR64) * 4u + off);
                #pragma unroll
                for (int mi = 0; mi < 2; mi++) {
                    mma_bf16(c[j][mi][0], afr[mi][0], afr[mi][1], afr[mi][2], afr[mi][3], b0, b2);
                    mma_bf16(c[j][mi][1], afr[mi][0], afr[mi][1], afr[mi][2], afr[mi][3], b1, b3);
                }
            }
        }
    }

    // epilogue: Horner in u + x*delta*S2, then silu
    #pragma unroll
    for (int mi = 0; mi < 2; mi++) {
        #pragma unroll
        for (int half = 0; half < 2; half++) {
            int rl = mi * 16 + g + half * 8;
            int r = row0 + rl;
            float s2 = s2s[rl];
            #pragma unroll
            for (int ni = 0; ni < 2; ni++) {
                int d = col0 + wn * 16 + ni * 8 + 2 * tig;
                float2 dl = *(const float2*)&g_DELTA[(size_t)r * D2 + d];
                float2 xc = __bfloat1622float2(
                    *(const __nv_bfloat162*)(g_XCbf + (size_t)r * D2 + d));
                int q0 = half * 2;
                float u0 = dl.x - LN2F, u1 = dl.y - LN2F;
                float s0 = c[0][mi][ni][q0]
                         + u0 * (c[1][mi][ni][q0] + u0 * (c[2][mi][ni][q0] + u0 * c[3][mi][ni][q0]));
                float s1 = c[0][mi][ni][q0 + 1]
                         + u1 * (c[1][mi][ni][q0 + 1] + u1 * (c[2][mi][ni][q0 + 1] + u1 * c[3][mi][ni][q0 + 1]));
                s0 += xc.x * dl.x * s2;
                s1 += xc.y * dl.y * s2;
                *(float2*)&g_XS[(size_t)r * D2 + d] = make_float2(silu_f(s0), silu_f(s1));
            }
        }
    }
}

// ---------------- out GEMM with fused comb (register-staged, BK=32) ----------
__global__ __launch_bounds__(128) void out_kernel(
    const float* __restrict__ out_W, const float* __restrict__ out_b,
    float* __restrict__ out)
{
    __shared__ uint32_t smbuf[OA32W + OB64W];
    uint32_t* As = smbuf;
    uint32_t* Bs = smbuf + OA32W;
    const int t = threadIdx.x;
    const int lane = t & 31, wn = t >> 5;
    const int g = lane >> 2, tig = lane & 3;
    const int row0 = blockIdx.y * 32, col0 = blockIdx.x * 64;
    const int ar = t >> 2, ac = (t & 3) * 8;
    const int N = Dm, K = D2;

    const float* Ap  = g_XS + (size_t)(row0 + ar) * K + ac;
    const float* A2p = g_XS + (size_t)(HROWS + row0 + ar) * K + ac;
    const float* A3p = g_RES + (size_t)(row0 + ar) * K + ac;
    const float* Wp0 = out_W + (size_t)(col0 + ar) * K + ac;
    const float* Wp1 = out_W + (size_t)(col0 + ar + 32) * K + ac;

    float c[2][2][4] = {};
    const int ntiles = K >> 5;
    uint4 ab, wb0, wb1;

#define LOAD_AB(ko) do { \
    float4 u = *(const float4*)(Ap + (ko)); \
    float4 v = *(const float4*)(Ap + (ko) + 4); \
    float4 u2 = *(const float4*)(A2p + (ko)), u3 = *(const float4*)(A3p + (ko)); \
    float4 v2 = *(const float4*)(A2p + (ko) + 4), v3 = *(const float4*)(A3p + (ko) + 4); \
    u.x = (u.x + u2.x) * u3.x; u.y = (u.y + u2.y) * u3.y; \
    u.z = (u.z + u2.z) * u3.z; u.w = (u.w + u2.w) * u3.w; \
    v.x = (v.x + v2.x) * v3.x; v.y = (v.y + v2.y) * v3.y; \
    v.z = (v.z + v2.z) * v3.z; v.w = (v.w + v2.w) * v3.w; \
    ab = pack8(u, v); \
    { float4 xx = *(const float4*)(Wp0 + (ko)); \
      float4 yy = *(const float4*)(Wp0 + (ko) + 4); \
      wb0 = pack8(xx, yy); } \
    { float4 xx = *(const float4*)(Wp1 + (ko)); \
      float4 yy = *(const float4*)(Wp1 + (ko) + 4); \
      wb1 = pack8(xx, yy); } \
} while (0)

    LOAD_AB(0);
    for (int kt = 0; kt < ntiles; kt++) {
        __syncthreads();
        *(uint4*)&As[ar * OSROW + (t & 3) * 4] = ab;
        *(uint4*)&Bs[ar * OSROW + (t & 3) * 4] = wb0;
        *(uint4*)&Bs[(ar + 32) * OSROW + (t & 3) * 4] = wb1;
        __syncthreads();
        if (kt + 1 < ntiles) LOAD_AB((kt + 1) * 32);
        #pragma unroll
        for (int k16 = 0; k16 < 2; k16++) {
            const int kb = k16 * 8;
            uint32_t afr[2][4], bfr[2][2];
            #pragma unroll
            for (int mi = 0; mi < 2; mi++) {
                int r = mi * 16 + g;
                afr[mi][0] = As[r * OSROW + kb + tig];
                afr[mi][1] = As[(r + 8) * OSROW + kb + tig];
                afr[mi][2] = As[r * OSROW + kb + tig + 4];
                afr[mi][3] = As[(r + 8) * OSROW + kb + tig + 4];
            }
            #pragma unroll
            for (int ni = 0; ni < 2; ni++) {
                int n = wn * 16 + ni * 8 + g;
                bfr[ni][0] = Bs[n * OSROW + kb + tig];
                bfr[ni][1] = Bs[n * OSROW + kb + tig + 4];
            }
            #pragma unroll
            for (int mi = 0; mi < 2; mi++)
                #pragma unroll
                for (int ni = 0; ni < 2; ni++)
                    mma_bf16(c[mi][ni], afr[mi][0], afr[mi][1], afr[mi][2],
                             afr[mi][3], bfr[ni][0], bfr[ni][1]);
        }
    }
#undef LOAD_AB

    #pragma unroll
    for (int mi = 0; mi < 2; mi++) {
        int r = row0 + mi * 16 + g;
        #pragma unroll
        for (int ni = 0; ni < 2; ni++) {
            int n = col0 + wn * 16 + ni * 8 + 2 * tig;
            float b0 = out_b[n], b1 = out_b[n + 1];
            *(float2*)&out[(size_t)r * N + n] =
                make_float2(c[mi][ni][0] + b0, c[mi][ni][1] + b1);
            *(float2*)&out[(size_t)(r + 8) * N + n] =
                make_float2(c[mi][ni][2] + b0, c[mi][ni][3] + b1);
        }
    }
}

// ---------------- launch ----------------
extern "C" void kernel_launch(void* const* d_in, const int* in_sizes, int n_in,
                              void* d_out, int out_size)
{
    const float* x      = (const float*)d_in[0];
    const float* mouth  = (const float*)d_in[1];
    const float* norm_w = (const float*)d_in[2];
    const float* inp_W  = (const float*)d_in[3];
    const float* inp_b  = (const float*)d_in[4];
    const float* out_W  = (const float*)d_in[5];
    const float* out_b  = (const float*)d_in[6];
    const float* Dlin_W = (const float*)d_in[7];
    const float* Dlin_b = (const float*)d_in[8];
    const float* conv_W = (const float*)d_in[9];
    const float* conv_b = (const float*)d_in[10];
    const float* fc1_W  = (const float*)d_in[11];
    const float* fc1_b  = (const float*)d_in[12];
    const float* fc2_W  = (const float*)d_in[13];
    const float* fc2_b  = (const float*)d_in[14];
    const float* A      = (const float*)d_in[15];

    const int SSM_SMEM = 2 * SST64 * 4;   // 82944 B
    cudaFuncSetAttribute(ssm_kernel,
                         cudaFuncAttributeMaxDynamicSharedMemorySize, SSM_SMEM);

    // 1) XNbf + E bf16 + weight bf16
    prep_kernel<<<672, 256>>>(x, mouth, norm_w, A, inp_W, Dlin_W, fc1_W, fc2_W);
    // 2) inp GEMM -> Pbf, res GEMM -> RES
    mega1_kernel<<<384, 128>>>(inp_b, Dlin_b);
    // 3) conv + silu -> XCbf
    conv_silu_kernel<<<128, 256>>>(conv_W, conv_b);
    // 4) delta GEMM -> DELTA, Bm GEMM -> BMbf
    mega2_kernel<<<320, 128>>>(fc1_b, fc2_b);
    // 5) ssm (4-slab GEMM + S2 + Horner + silu) -> XS
    ssm_kernel<<<dim3(D2 / 64, NROWS / 32), 128, SSM_SMEM>>>();
    // 6) out = ((XS_x + XS_m) * RES) @ out_W^T + out_b
    out_kernel<<<dim3(Dm / 64, HROWS / 32), 128>>>(out_W, out_b, (float*)d_out);
}